// round 5
// baseline (speedup 1.0000x reference)
#include <cuda_runtime.h>
#include <cstdint>

// QuantileLoss: mean over [N,5] loss built from preds[N,5], target[N,3].
// R5: persistent blocks + double-buffered cp.async pipeline.
//     Tile = 256 quads = 32KB (preds 20KB + target 12KB), 2 buffers = 64KB dynamic smem.
//     Grid = 3*148 persistent blocks, wait_group 1 overlaps next-tile load with compute.

__global__ void zero_out_kernel(float* out) {
    if (threadIdx.x == 0) out[0] = 0.0f;
}

__device__ __forceinline__ void cp_async16(uint32_t saddr, const void* gptr) {
    asm volatile("cp.async.cg.shared.global [%0], [%1], 16;\n"
                 :: "r"(saddr), "l"(gptr));
}

__device__ __forceinline__ float row_loss(
    float p0, float p1, float p2, float p3, float p4,
    float t0, float t1, float t2)
{
    float d0 = p0 - t0;
    float d1 = p1 - t1;
    float d2 = p2 - t2;
    float main_mse = d0 * d0 + d1 * d1 + d2 * d2;

    float pen = (p4 - t2) * 4.0f;

    float lo_th = t2 * 0.95f;
    float lo_d  = p3 - lo_th;
    float lower = (p3 > p2) ? pen : ((p3 > lo_th) ? 0.0f : lo_d * lo_d);

    float up_th = t2 * 1.05f;
    float up_d  = p4 - up_th;
    float upper = (p4 < p2) ? pen : ((p4 < up_th) ? 0.0f : up_d * up_d);

    return main_mse + lower + upper;
}

__device__ __forceinline__ float quad_rows(
    float4 p0, float4 p1, float4 p2, float4 p3, float4 p4,
    float4 g0, float4 g1, float4 g2)
{
    float s;
    s  = row_loss(p0.x, p0.y, p0.z, p0.w, p1.x, g0.x, g0.y, g0.z);
    s += row_loss(p1.y, p1.z, p1.w, p2.x, p2.y, g0.w, g1.x, g1.y);
    s += row_loss(p2.z, p2.w, p3.x, p3.y, p3.z, g1.z, g1.w, g2.x);
    s += row_loss(p3.w, p4.x, p4.y, p4.z, p4.w, g2.y, g2.z, g2.w);
    return s;
}

// Tile layout inside one 2048-float4 buffer:
//   [0..1279]    preds  (256 quads * 5 float4)
//   [1280..2047] target (256 quads * 3 float4)
// Flattened load: 1024 float4 slots per HALF... no: total 2048 f4 per tile,
// 256 threads * 8 cp.async each (5 preds-strips + 3 target-strips).

__global__ void __launch_bounds__(256)
quantile_loss_kernel(const float4* __restrict__ preds4,
                     const float4* __restrict__ tgt4,
                     const float*  __restrict__ preds,
                     const float*  __restrict__ target,
                     float* __restrict__ out,
                     int nquads, int n_rows, float inv_count)
{
    extern __shared__ float4 sh[];   // 2 buffers * 2048 float4 = 64 KB
    const int tid = threadIdx.x;
    const uint32_t sbase = (uint32_t)__cvta_generic_to_shared(sh);

    const int ntiles = nquads >> 8;          // full 256-quad tiles
    float s = 0.0f;

    // ---- prologue: prefetch first tile into buffer 0 ----
    int tile = blockIdx.x;
    if (tile < ntiles) {
        const float4* pg = preds4 + (size_t)tile * 1280;
        const float4* tg = tgt4   + (size_t)tile * 768;
        #pragma unroll
        for (int k = 0; k < 5; k++)
            cp_async16(sbase + (uint32_t)(k * 256 + tid) * 16u, pg + k * 256 + tid);
        #pragma unroll
        for (int k = 0; k < 3; k++)
            cp_async16(sbase + (uint32_t)(1280 + k * 256 + tid) * 16u, tg + k * 256 + tid);
        asm volatile("cp.async.commit_group;\n" ::: "memory");
    }

    int buf = 0;
    for (; tile < ntiles; tile += gridDim.x) {
        int next = tile + gridDim.x;
        if (next < ntiles) {
            // prefetch next tile into the other buffer
            uint32_t nb = sbase + (uint32_t)(buf ^ 1) * 2048u * 16u;
            const float4* pg = preds4 + (size_t)next * 1280;
            const float4* tg = tgt4   + (size_t)next * 768;
            #pragma unroll
            for (int k = 0; k < 5; k++)
                cp_async16(nb + (uint32_t)(k * 256 + tid) * 16u, pg + k * 256 + tid);
            #pragma unroll
            for (int k = 0; k < 3; k++)
                cp_async16(nb + (uint32_t)(1280 + k * 256 + tid) * 16u, tg + k * 256 + tid);
            asm volatile("cp.async.commit_group;\n" ::: "memory");
            asm volatile("cp.async.wait_group 1;\n" ::: "memory");
        } else {
            asm volatile("cp.async.wait_group 0;\n" ::: "memory");
        }
        __syncthreads();   // current buffer fully landed for all threads

        const float4* b = sh + buf * 2048;
        float4 p0 = b[tid * 5 + 0];
        float4 p1 = b[tid * 5 + 1];
        float4 p2 = b[tid * 5 + 2];
        float4 p3 = b[tid * 5 + 3];
        float4 p4 = b[tid * 5 + 4];
        float4 g0 = b[1280 + tid * 3 + 0];
        float4 g1 = b[1280 + tid * 3 + 1];
        float4 g2 = b[1280 + tid * 3 + 2];

        s += quad_rows(p0, p1, p2, p3, p4, g0, g1, g2);

        buf ^= 1;
        __syncthreads();   // all compute reads done before this buffer is reloaded
    }

    // ---- remainder quads (nquads % 256) : block 0, direct loads ----
    if (blockIdx.x == 0) {
        int q = (ntiles << 8) + tid;
        if (q < nquads) {
            float4 p0 = preds4[q * 5 + 0];
            float4 p1 = preds4[q * 5 + 1];
            float4 p2 = preds4[q * 5 + 2];
            float4 p3 = preds4[q * 5 + 3];
            float4 p4 = preds4[q * 5 + 4];
            float4 g0 = tgt4[q * 3 + 0];
            float4 g1 = tgt4[q * 3 + 1];
            float4 g2 = tgt4[q * 3 + 2];
            s += quad_rows(p0, p1, p2, p3, p4, g0, g1, g2);
        }
        // tail rows (n_rows % 4)
        if (tid == 0) {
            for (int r = nquads * 4; r < n_rows; r++) {
                s += row_loss(preds[r * 5 + 0], preds[r * 5 + 1], preds[r * 5 + 2],
                              preds[r * 5 + 3], preds[r * 5 + 4],
                              target[r * 3 + 0], target[r * 3 + 1], target[r * 3 + 2]);
            }
        }
    }

    // ---- intra-block reduce ----
    #pragma unroll
    for (int off = 16; off > 0; off >>= 1)
        s += __shfl_down_sync(0xFFFFFFFFu, s, off);

    __syncthreads();
    float* ws = (float*)sh;
    int lane = tid & 31;
    int wid  = tid >> 5;
    if (lane == 0) ws[wid] = s;
    __syncthreads();

    if (wid == 0) {
        s = (lane < 8) ? ws[lane] : 0.0f;
        #pragma unroll
        for (int off = 4; off > 0; off >>= 1)
            s += __shfl_down_sync(0xFFFFFFFFu, s, off);
        if (lane == 0)
            atomicAdd(out, s * inv_count);
    }
}

extern "C" void kernel_launch(void* const* d_in, const int* in_sizes, int n_in,
                              void* d_out, int out_size)
{
    const float* preds  = (const float*)d_in[0];
    const float* target = (const float*)d_in[1];
    float* out = (float*)d_out;

    int n_rows = in_sizes[0] / 5;
    int nquads = n_rows / 4;
    float inv_count = 1.0f / (5.0f * (float)n_rows);

    const int smem_bytes = 2 * 2048 * 16;   // 64 KB
    cudaFuncSetAttribute(quantile_loss_kernel,
                         cudaFuncAttributeMaxDynamicSharedMemorySize, smem_bytes);

    zero_out_kernel<<<1, 32>>>(out);

    int ntiles = nquads >> 8;
    int blocks = 3 * 148;                    // persistent: 3 CTAs per SM
    if (ntiles < blocks) blocks = (ntiles > 0) ? ntiles : 1;

    quantile_loss_kernel<<<blocks, 256, smem_bytes>>>(
        (const float4*)preds, (const float4*)target,
        preds, target, out, nquads, n_rows, inv_count);
}